// round 1
// baseline (speedup 1.0000x reference)
#include <cuda_runtime.h>

#define BB 8
#define HH 1024
#define WW 1024
#define VV 35709
#define TT 70789
#define HWSZ (HH * WW)
#define NPX (BB * HWSZ)

__device__ __forceinline__ float clamp01(float x) {
    return fminf(fmaxf(x, 0.0f), 1.0f);
}

__global__ __launch_bounds__(256) void raster_kernel(
    const int*   __restrict__ ids,     // [B,H,W]
    const float* __restrict__ bary,    // [B,H,W,3]
    const float* __restrict__ colors,  // [B,V,3]
    const int*   __restrict__ tris,    // [T,3]
    float*       __restrict__ out)     // images [B,3,H,W] ++ alphas [B,1,H,W]
{
    int q = blockIdx.x * blockDim.x + threadIdx.x;   // quad index (4 px each)
    if (q >= NPX / 4) return;
    int p  = q << 2;
    int b  = p / HWSZ;
    int hw = p - b * HWSZ;

    const float* cb = colors + (size_t)b * (VV * 3);

    int4   t4  = *reinterpret_cast<const int4*>(ids + p);
    const float4* bv = reinterpret_cast<const float4*>(bary + (size_t)p * 3);
    float4 by0 = bv[0];
    float4 by1 = bv[1];
    float4 by2 = bv[2];

    float bx[4][3] = {
        { by0.x, by0.y, by0.z },
        { by0.w, by1.x, by1.y },
        { by1.z, by1.w, by2.x },
        { by2.y, by2.z, by2.w }
    };
    int tid[4] = { t4.x, t4.y, t4.z, t4.w };

    float rr[4], gg[4], bb_[4], aa[4];

#pragma unroll
    for (int i = 0; i < 4; ++i) {
        int t  = tid[i];
        int v0 = __ldg(tris + 3 * t + 0);
        int v1 = __ldg(tris + 3 * t + 1);
        int v2 = __ldg(tris + 3 * t + 2);

        float b0 = bx[i][0], b1 = bx[i][1], b2 = bx[i][2];

        float c0r = __ldg(cb + 3 * v0 + 0);
        float c0g = __ldg(cb + 3 * v0 + 1);
        float c0b = __ldg(cb + 3 * v0 + 2);
        float c1r = __ldg(cb + 3 * v1 + 0);
        float c1g = __ldg(cb + 3 * v1 + 1);
        float c1b = __ldg(cb + 3 * v1 + 2);
        float c2r = __ldg(cb + 3 * v2 + 0);
        float c2g = __ldg(cb + 3 * v2 + 1);
        float c2b = __ldg(cb + 3 * v2 + 2);

        rr[i]  = clamp01(fmaf(b0, c0r, fmaf(b1, c1r, b2 * c2r)));
        gg[i]  = clamp01(fmaf(b0, c0g, fmaf(b1, c1g, b2 * c2g)));
        bb_[i] = clamp01(fmaf(b0, c0b, fmaf(b1, c1b, b2 * c2b)));
        aa[i]  = clamp01(2.0f * (b0 + b1 + b2));
    }

    size_t img_base = (size_t)b * 3 * HWSZ + hw;
    *reinterpret_cast<float4*>(out + img_base)             = make_float4(rr[0], rr[1], rr[2], rr[3]);
    *reinterpret_cast<float4*>(out + img_base + HWSZ)      = make_float4(gg[0], gg[1], gg[2], gg[3]);
    *reinterpret_cast<float4*>(out + img_base + 2 * HWSZ)  = make_float4(bb_[0], bb_[1], bb_[2], bb_[3]);

    size_t a_base = (size_t)BB * 3 * HWSZ + (size_t)b * HWSZ + hw;
    *reinterpret_cast<float4*>(out + a_base) = make_float4(aa[0], aa[1], aa[2], aa[3]);
}

extern "C" void kernel_launch(void* const* d_in, const int* in_sizes, int n_in,
                              void* d_out, int out_size) {
    const int*   ids    = (const int*)d_in[0];
    const float* bary   = (const float*)d_in[1];
    const float* colors = (const float*)d_in[2];
    const int*   tris   = (const int*)d_in[3];
    float*       out    = (float*)d_out;

    int quads   = NPX / 4;                 // 2,097,152
    int threads = 256;
    int blocks  = (quads + threads - 1) / threads;
    raster_kernel<<<blocks, threads>>>(ids, bary, colors, tris, out);
}

// round 2
// speedup vs baseline: 1.6953x; 1.6953x over previous
#include <cuda_runtime.h>

#define BB 8
#define HH 1024
#define WW 1024
#define VV 35709
#define TT 70789
#define HWSZ (HH * WW)
#define NPX (BB * HWSZ)

// Packed per-(batch,triangle) corner colors: 12 floats (48B) per entry.
// Layout: [c0r c0g c0b c1r | c1g c1b c2r c2g | c2b pad pad pad]
__device__ float g_packed[(size_t)BB * TT * 12];

__device__ __forceinline__ float clamp01(float x) {
    return fminf(fmaxf(x, 0.0f), 1.0f);
}

__global__ __launch_bounds__(256) void build_table(
    const float* __restrict__ colors,  // [B,V,3]
    const int*   __restrict__ tris)    // [T,3]
{
    int t = blockIdx.x * blockDim.x + threadIdx.x;
    int b = blockIdx.y;
    if (t >= TT) return;

    int v0 = __ldg(tris + 3 * t + 0);
    int v1 = __ldg(tris + 3 * t + 1);
    int v2 = __ldg(tris + 3 * t + 2);

    const float* cb = colors + (size_t)b * (VV * 3);

    float c0r = __ldg(cb + 3 * v0 + 0);
    float c0g = __ldg(cb + 3 * v0 + 1);
    float c0b = __ldg(cb + 3 * v0 + 2);
    float c1r = __ldg(cb + 3 * v1 + 0);
    float c1g = __ldg(cb + 3 * v1 + 1);
    float c1b = __ldg(cb + 3 * v1 + 2);
    float c2r = __ldg(cb + 3 * v2 + 0);
    float c2g = __ldg(cb + 3 * v2 + 1);
    float c2b = __ldg(cb + 3 * v2 + 2);

    float4* dst = reinterpret_cast<float4*>(g_packed + ((size_t)b * TT + t) * 12);
    dst[0] = make_float4(c0r, c0g, c0b, c1r);
    dst[1] = make_float4(c1g, c1b, c2r, c2g);
    dst[2] = make_float4(c2b, 0.0f, 0.0f, 0.0f);
}

__global__ __launch_bounds__(256) void raster_kernel(
    const int*   __restrict__ ids,     // [B,H,W]
    const float* __restrict__ bary,    // [B,H,W,3]
    float*       __restrict__ out)     // images [B,3,H,W] ++ alphas [B,1,H,W]
{
    int q = blockIdx.x * blockDim.x + threadIdx.x;   // quad index (4 px each)
    if (q >= NPX / 4) return;
    int p  = q << 2;
    int b  = p / HWSZ;
    int hw = p - b * HWSZ;

    int4   t4  = *reinterpret_cast<const int4*>(ids + p);
    const float4* bv = reinterpret_cast<const float4*>(bary + (size_t)p * 3);
    float4 by0 = bv[0];
    float4 by1 = bv[1];
    float4 by2 = bv[2];

    float bx[4][3] = {
        { by0.x, by0.y, by0.z },
        { by0.w, by1.x, by1.y },
        { by1.z, by1.w, by2.x },
        { by2.y, by2.z, by2.w }
    };
    int tid[4] = { t4.x, t4.y, t4.z, t4.w };

    const float* tab_b = g_packed + (size_t)b * TT * 12;

    float rr[4], gg[4], bb_[4], aa[4];

#pragma unroll
    for (int i = 0; i < 4; ++i) {
        const float4* e = reinterpret_cast<const float4*>(tab_b + (size_t)tid[i] * 12);
        float4 e0 = __ldg(e + 0);
        float4 e1 = __ldg(e + 1);
        float4 e2 = __ldg(e + 2);

        float b0 = bx[i][0], b1 = bx[i][1], b2 = bx[i][2];

        rr[i]  = clamp01(fmaf(b0, e0.x, fmaf(b1, e0.w, b2 * e1.z)));
        gg[i]  = clamp01(fmaf(b0, e0.y, fmaf(b1, e1.x, b2 * e1.w)));
        bb_[i] = clamp01(fmaf(b0, e0.z, fmaf(b1, e1.y, b2 * e2.x)));
        aa[i]  = clamp01(2.0f * (b0 + b1 + b2));
    }

    size_t img_base = (size_t)b * 3 * HWSZ + hw;
    *reinterpret_cast<float4*>(out + img_base)             = make_float4(rr[0], rr[1], rr[2], rr[3]);
    *reinterpret_cast<float4*>(out + img_base + HWSZ)      = make_float4(gg[0], gg[1], gg[2], gg[3]);
    *reinterpret_cast<float4*>(out + img_base + 2 * HWSZ)  = make_float4(bb_[0], bb_[1], bb_[2], bb_[3]);

    size_t a_base = (size_t)BB * 3 * HWSZ + (size_t)b * HWSZ + hw;
    *reinterpret_cast<float4*>(out + a_base) = make_float4(aa[0], aa[1], aa[2], aa[3]);
}

extern "C" void kernel_launch(void* const* d_in, const int* in_sizes, int n_in,
                              void* d_out, int out_size) {
    const int*   ids    = (const int*)d_in[0];
    const float* bary   = (const float*)d_in[1];
    const float* colors = (const float*)d_in[2];
    const int*   tris   = (const int*)d_in[3];
    float*       out    = (float*)d_out;

    dim3 g1((TT + 255) / 256, BB);
    build_table<<<g1, 256>>>(colors, tris);

    int quads   = NPX / 4;                 // 2,097,152
    int blocks  = (quads + 255) / 256;
    raster_kernel<<<blocks, 256>>>(ids, bary, out);
}

// round 3
// speedup vs baseline: 2.5751x; 1.5190x over previous
#include <cuda_runtime.h>
#include <cstdint>

#define BB 8
#define HH 1024
#define WW 1024
#define VV 35709
#define TT 70789
#define HWSZ (HH * WW)
#define NPX (BB * HWSZ)

// Stage A output: per-(batch,vertex) quantized color, 3 x u14 packed in u64 (42 bits)
__device__ uint64_t g_vcol[(size_t)BB * VV];
// Stage B output: per-(batch,triangle) 9 x u14 packed in 128 bits
__device__ uint4 g_packed[(size_t)BB * TT];

__device__ __forceinline__ float clamp01(float x) {
    return fminf(fmaxf(x, 0.0f), 1.0f);
}

__device__ __forceinline__ uint32_t q14(float c) {
    // round-to-nearest u14 in [0, 16383]
    float f = fminf(fmaf(c, 16384.0f, 0.5f), 16383.0f);
    return (uint32_t)f;
}

// ── Stage A: quantize per-(b,v) colors, coalesced ──────────────────────────
__global__ __launch_bounds__(256) void quant_vcol(
    const float* __restrict__ colors)  // [B,V,3]
{
    int idx = blockIdx.x * blockDim.x + threadIdx.x;
    if (idx >= BB * VV) return;
    float r = colors[3 * idx + 0];
    float g = colors[3 * idx + 1];
    float b = colors[3 * idx + 2];
    uint64_t qv = (uint64_t)q14(r) | ((uint64_t)q14(g) << 14) | ((uint64_t)q14(b) << 28);
    g_vcol[idx] = qv;
}

// ── Stage B: gather 3 vertices per (b,t), merge into one uint4 ─────────────
__global__ __launch_bounds__(256) void build_table(
    const int* __restrict__ tris)      // [T,3]
{
    int t = blockIdx.x * blockDim.x + threadIdx.x;
    int b = blockIdx.y;
    if (t >= TT) return;

    int v0 = __ldg(tris + 3 * t + 0);
    int v1 = __ldg(tris + 3 * t + 1);
    int v2 = __ldg(tris + 3 * t + 2);

    const uint64_t* vb = g_vcol + (size_t)b * VV;
    uint64_t q0 = __ldg(vb + v0);
    uint64_t q1 = __ldg(vb + v1);
    uint64_t q2 = __ldg(vb + v2);

    // fields at bit offsets 14*i: v0 bits[0,42), v1 [42,84), v2 [84,126)
    uint64_t lo = q0 | (q1 << 42);
    uint64_t hi = (q1 >> 22) | (q2 << 20);

    g_packed[(size_t)b * TT + t] =
        make_uint4((uint32_t)lo, (uint32_t)(lo >> 32),
                   (uint32_t)hi, (uint32_t)(hi >> 32));
}

// ── Pass 2: one 16B gather per pixel ───────────────────────────────────────
__global__ __launch_bounds__(256) void raster_kernel(
    const int*   __restrict__ ids,     // [B,H,W]
    const float* __restrict__ bary,    // [B,H,W,3]
    float*       __restrict__ out)     // images [B,3,H,W] ++ alphas [B,1,H,W]
{
    int q = blockIdx.x * blockDim.x + threadIdx.x;   // quad index (4 px)
    if (q >= NPX / 4) return;
    int p  = q << 2;
    int b  = p / HWSZ;
    int hw = p - b * HWSZ;

    int4   t4  = *reinterpret_cast<const int4*>(ids + p);
    const float4* bv = reinterpret_cast<const float4*>(bary + (size_t)p * 3);
    float4 by0 = bv[0];
    float4 by1 = bv[1];
    float4 by2 = bv[2];

    float bx[4][3] = {
        { by0.x, by0.y, by0.z },
        { by0.w, by1.x, by1.y },
        { by1.z, by1.w, by2.x },
        { by2.y, by2.z, by2.w }
    };
    int tid[4] = { t4.x, t4.y, t4.z, t4.w };

    const uint4* tab_b = g_packed + (size_t)b * TT;

    const float S = 1.0f / 16384.0f;
    float rr[4], gg[4], bb_[4], aa[4];

#pragma unroll
    for (int i = 0; i < 4; ++i) {
        uint4 e = __ldg(tab_b + tid[i]);
        uint32_t w0 = e.x, w1 = e.y, w2 = e.z, w3 = e.w;

        // decode 9 x u14 at bit offsets 14*k
        float f0 = (float)(int)( w0        & 0x3FFFu);                       // c0.r
        float f1 = (float)(int)((w0 >> 14) & 0x3FFFu);                       // c0.g
        float f2 = (float)(int)(__funnelshift_r(w0, w1, 28) & 0x3FFFu);      // c0.b
        float f3 = (float)(int)((w1 >> 10) & 0x3FFFu);                       // c1.r
        float f4 = (float)(int)(__funnelshift_r(w1, w2, 24) & 0x3FFFu);      // c1.g
        float f5 = (float)(int)((w2 >>  6) & 0x3FFFu);                       // c1.b
        float f6 = (float)(int)(__funnelshift_r(w2, w3, 20) & 0x3FFFu);      // c2.r
        float f7 = (float)(int)((w3 >>  2) & 0x3FFFu);                       // c2.g
        float f8 = (float)(int)((w3 >> 16) & 0x3FFFu);                       // c2.b

        float b0 = bx[i][0], b1 = bx[i][1], b2 = bx[i][2];
        float s0 = b0 * S, s1 = b1 * S, s2 = b2 * S;

        rr[i]  = clamp01(fmaf(s0, f0, fmaf(s1, f3, s2 * f6)));
        gg[i]  = clamp01(fmaf(s0, f1, fmaf(s1, f4, s2 * f7)));
        bb_[i] = clamp01(fmaf(s0, f2, fmaf(s1, f5, s2 * f8)));
        aa[i]  = clamp01(2.0f * (b0 + b1 + b2));
    }

    size_t img_base = (size_t)b * 3 * HWSZ + hw;
    *reinterpret_cast<float4*>(out + img_base)             = make_float4(rr[0], rr[1], rr[2], rr[3]);
    *reinterpret_cast<float4*>(out + img_base + HWSZ)      = make_float4(gg[0], gg[1], gg[2], gg[3]);
    *reinterpret_cast<float4*>(out + img_base + 2 * HWSZ)  = make_float4(bb_[0], bb_[1], bb_[2], bb_[3]);

    size_t a_base = (size_t)BB * 3 * HWSZ + (size_t)b * HWSZ + hw;
    *reinterpret_cast<float4*>(out + a_base) = make_float4(aa[0], aa[1], aa[2], aa[3]);
}

extern "C" void kernel_launch(void* const* d_in, const int* in_sizes, int n_in,
                              void* d_out, int out_size) {
    const int*   ids    = (const int*)d_in[0];
    const float* bary   = (const float*)d_in[1];
    const float* colors = (const float*)d_in[2];
    const int*   tris   = (const int*)d_in[3];
    float*       out    = (float*)d_out;

    quant_vcol<<<(BB * VV + 255) / 256, 256>>>(colors);

    dim3 g1((TT + 255) / 256, BB);
    build_table<<<g1, 256>>>(tris);

    int quads  = NPX / 4;                 // 2,097,152
    int blocks = (quads + 255) / 256;
    raster_kernel<<<blocks, 256>>>(ids, bary, out);
}